// round 2
// baseline (speedup 1.0000x reference)
#include <cuda_runtime.h>

// ChannelDropout:
//   row = (b, c) of 64*273 = 17472 rows, each row = 3000 f32 (= 750 float4, 16B aligned).
//   kept   = ||pos(row) - center||^2 > 0.04
//   proba  = (1/100) * sum_n [ ||pos(row) - mc[n]||^2 > 0.04 ]
//   scale  = kept ? 1/(1e-8 + proba) : 0
//   out[row, t] = sig[row, t] * scale
//
// One block per row; 256 threads; each thread owns up to 3 float4 of the row.
// Loads are issued BEFORE the scale computation so the ~100-iter MC loop hides
// under the in-flight LDG.128s (memory-bound kernel, HBM is the roofline).

#define DROPOUT2 0.04f   // 0.2^2
#define EPSILON  1e-8f
#define T4       750     // 3000 floats / 4
#define NMC      100

__global__ __launch_bounds__(256, 8)
void channel_dropout_kernel(const float* __restrict__ sig,
                            const float* __restrict__ pos,
                            const float* __restrict__ center,
                            const float* __restrict__ mc,
                            float* __restrict__ out)
{
    const int row = blockIdx.x;           // 0 .. 17471
    const int tid = threadIdx.x;          // 0 .. 255

    const float4* __restrict__ s4 = (const float4*)(sig) + (size_t)row * T4;
    float4*       __restrict__ o4 = (float4*)(out)       + (size_t)row * T4;

    // --- issue the row loads first (independent of scale) ---
    const int i0 = tid;
    const int i1 = tid + 256;
    const int i2 = tid + 512;
    const bool has2 = (i2 < T4);          // tid < 238

    float4 v0 = s4[i0];
    float4 v1 = s4[i1];
    float4 v2 = has2 ? s4[i2] : make_float4(0.f, 0.f, 0.f, 0.f);

    // --- per-row scalar: kept + MC keep-probability ---
    const float px = __ldg(&pos[row * 2 + 0]);
    const float py = __ldg(&pos[row * 2 + 1]);
    const float cx = __ldg(&center[0]);
    const float cy = __ldg(&center[1]);

    const float dx = px - cx, dy = py - cy;
    const bool kept = (dx * dx + dy * dy) > DROPOUT2;

    int cnt = 0;
    #pragma unroll
    for (int n = 0; n < NMC; ++n) {
        const float ax = px - __ldg(&mc[2 * n + 0]);
        const float ay = py - __ldg(&mc[2 * n + 1]);
        cnt += (ax * ax + ay * ay) > DROPOUT2 ? 1 : 0;
    }

    const float proba = __int2float_rn(cnt) * (1.0f / NMC);  // exact for cnt<=100 up to 1ulp
    const float scale = kept ? (1.0f / (EPSILON + proba)) : 0.0f;

    // --- scale + store ---
    v0.x *= scale; v0.y *= scale; v0.z *= scale; v0.w *= scale;
    v1.x *= scale; v1.y *= scale; v1.z *= scale; v1.w *= scale;
    o4[i0] = v0;
    o4[i1] = v1;
    if (has2) {
        v2.x *= scale; v2.y *= scale; v2.z *= scale; v2.w *= scale;
        o4[i2] = v2;
    }
}

extern "C" void kernel_launch(void* const* d_in, const int* in_sizes, int n_in,
                              void* d_out, int out_size)
{
    const float* sig    = (const float*)d_in[0];  // (64, 273, 3000) f32
    const float* pos    = (const float*)d_in[1];  // (64, 273, 2)    f32
    const float* center = (const float*)d_in[2];  // (2,)            f32
    const float* mc     = (const float*)d_in[3];  // (100, 2)        f32
    float* out          = (float*)d_out;          // (64, 273, 3000) f32

    const int rows = 64 * 273;                    // 17472
    channel_dropout_kernel<<<rows, 256>>>(sig, pos, center, mc, out);
}

// round 3
// speedup vs baseline: 3.1164x; 3.1164x over previous
#include <cuda_runtime.h>

// ChannelDropout — two-phase:
//   Phase 1 (tiny): per-row scale = kept(row) / (eps + MC keep probability)
//                   one thread per row, 100-iter MC loop, writes g_scale.
//   Phase 2 (stream): out[row,t] = sig[row,t] * g_scale[row]
//                     pure HBM stream, 420 MB total traffic.

#define DROPOUT2 0.04f   // 0.2^2
#define EPSILON  1e-8f
#define T4       750     // 3000 floats / 4
#define NMC      100
#define ROWS     (64 * 273)   // 17472

__device__ float g_scale[ROWS];

__global__ __launch_bounds__(256)
void scale_kernel(const float* __restrict__ pos,
                  const float* __restrict__ center,
                  const float* __restrict__ mc)
{
    const int row = blockIdx.x * 256 + threadIdx.x;
    if (row >= ROWS) return;

    const float px = pos[row * 2 + 0];
    const float py = pos[row * 2 + 1];
    const float cx = __ldg(&center[0]);
    const float cy = __ldg(&center[1]);

    const float dx = px - cx, dy = py - cy;
    const bool kept = (dx * dx + dy * dy) > DROPOUT2;

    int cnt = 0;
    #pragma unroll
    for (int n = 0; n < NMC; ++n) {
        const float ax = px - __ldg(&mc[2 * n + 0]);
        const float ay = py - __ldg(&mc[2 * n + 1]);
        cnt += (ax * ax + ay * ay) > DROPOUT2 ? 1 : 0;
    }

    const float proba = __int2float_rn(cnt) * (1.0f / NMC);
    g_scale[row] = kept ? (1.0f / (EPSILON + proba)) : 0.0f;
}

__global__ __launch_bounds__(256, 8)
void stream_kernel(const float* __restrict__ sig,
                   float* __restrict__ out)
{
    const int row = blockIdx.x;
    const int tid = threadIdx.x;

    const float4* __restrict__ s4 = (const float4*)(sig) + (size_t)row * T4;
    float4*       __restrict__ o4 = (float4*)(out)       + (size_t)row * T4;

    // Uniform load — all threads hit the same address (L1 broadcast).
    const float scale = __ldg(&g_scale[row]);

    const int i0 = tid;
    const int i1 = tid + 256;
    const int i2 = tid + 512;
    const bool has2 = (i2 < T4);       // tid < 238

    float4 v0 = s4[i0];
    float4 v1 = s4[i1];
    float4 v2 = has2 ? s4[i2] : make_float4(0.f, 0.f, 0.f, 0.f);

    v0.x *= scale; v0.y *= scale; v0.z *= scale; v0.w *= scale;
    v1.x *= scale; v1.y *= scale; v1.z *= scale; v1.w *= scale;
    o4[i0] = v0;
    o4[i1] = v1;
    if (has2) {
        v2.x *= scale; v2.y *= scale; v2.z *= scale; v2.w *= scale;
        o4[i2] = v2;
    }
}

extern "C" void kernel_launch(void* const* d_in, const int* in_sizes, int n_in,
                              void* d_out, int out_size)
{
    const float* sig    = (const float*)d_in[0];  // (64, 273, 3000) f32
    const float* pos    = (const float*)d_in[1];  // (64, 273, 2)    f32
    const float* center = (const float*)d_in[2];  // (2,)            f32
    const float* mc     = (const float*)d_in[3];  // (100, 2)        f32
    float* out          = (float*)d_out;

    scale_kernel<<<(ROWS + 255) / 256, 256>>>(pos, center, mc);
    stream_kernel<<<ROWS, 256>>>(sig, out);
}

// round 4
// speedup vs baseline: 3.3429x; 1.0727x over previous
#include <cuda_runtime.h>

// ChannelDropout — fully fused, barrier-free:
//   One block per row (17472 rows x 3000 f32). Each warp cooperatively computes
//   the MC keep-count via 4 ballots (lane l checks mc[l], mc[l+32], mc[l+64],
//   and mc[l+96] for l<4) — no smem, no __syncthreads. Row loads issue first
//   so the scalar work hides under the in-flight LDG.128s.

#define DROPOUT2 0.04f   // 0.2^2
#define EPSILON  1e-8f
#define T4       750     // 3000 floats / 4
#define ROWS     (64 * 273)   // 17472

__global__ __launch_bounds__(256, 8)
void fused_kernel(const float* __restrict__ sig,
                  const float* __restrict__ pos,
                  const float* __restrict__ center,
                  const float* __restrict__ mc,
                  float* __restrict__ out)
{
    const int row  = blockIdx.x;
    const int tid  = threadIdx.x;
    const int lane = tid & 31;

    const float4* __restrict__ s4 = (const float4*)(sig) + (size_t)row * T4;
    float4*       __restrict__ o4 = (float4*)(out)       + (size_t)row * T4;

    // --- issue row loads first (independent of everything below) ---
    const int i0 = tid;
    const int i1 = tid + 256;
    const int i2 = tid + 512;
    const bool has2 = (i2 < T4);       // tid < 238

    float4 v0 = s4[i0];
    float4 v1 = s4[i1];
    float4 v2 = has2 ? s4[i2] : make_float4(0.f, 0.f, 0.f, 0.f);

    // --- per-row scalar, warp-cooperative (no barriers, no smem) ---
    const float px = __ldg(&pos[row * 2 + 0]);   // broadcast within block
    const float py = __ldg(&pos[row * 2 + 1]);
    const float cx = __ldg(&center[0]);
    const float cy = __ldg(&center[1]);

    // lane l checks MC centers l, l+32, l+64, (l+96 if l<4)
    float ax, ay;
    ax = px - __ldg(&mc[2 * lane + 0]);
    ay = px;  // placeholder avoided; recompute properly below
    // check 0
    ax = px - __ldg(&mc[2 * (lane) + 0]);
    ay = py - __ldg(&mc[2 * (lane) + 1]);
    const bool f0 = (ax * ax + ay * ay) > DROPOUT2;
    // check 1
    ax = px - __ldg(&mc[2 * (lane + 32) + 0]);
    ay = py - __ldg(&mc[2 * (lane + 32) + 1]);
    const bool f1 = (ax * ax + ay * ay) > DROPOUT2;
    // check 2
    ax = px - __ldg(&mc[2 * (lane + 64) + 0]);
    ay = py - __ldg(&mc[2 * (lane + 64) + 1]);
    const bool f2 = (ax * ax + ay * ay) > DROPOUT2;
    // check 3 (only lanes 0-3 valid: indices 96..99)
    bool f3 = false;
    if (lane < 4) {
        ax = px - __ldg(&mc[2 * (lane + 96) + 0]);
        ay = py - __ldg(&mc[2 * (lane + 96) + 1]);
        f3 = (ax * ax + ay * ay) > DROPOUT2;
    }

    const unsigned b0 = __ballot_sync(0xFFFFFFFFu, f0);
    const unsigned b1 = __ballot_sync(0xFFFFFFFFu, f1);
    const unsigned b2 = __ballot_sync(0xFFFFFFFFu, f2);
    const unsigned b3 = __ballot_sync(0xFFFFFFFFu, f3);

    const int cnt = __popc(b0) + __popc(b1) + __popc(b2) + __popc(b3 & 0xFu);

    const float dx = px - cx, dy = py - cy;
    const bool kept = (dx * dx + dy * dy) > DROPOUT2;

    const float proba = __int2float_rn(cnt) * 0.01f;
    const float scale = kept ? (1.0f / (EPSILON + proba)) : 0.0f;

    // --- scale + store ---
    v0.x *= scale; v0.y *= scale; v0.z *= scale; v0.w *= scale;
    v1.x *= scale; v1.y *= scale; v1.z *= scale; v1.w *= scale;
    o4[i0] = v0;
    o4[i1] = v1;
    if (has2) {
        v2.x *= scale; v2.y *= scale; v2.z *= scale; v2.w *= scale;
        o4[i2] = v2;
    }
}

extern "C" void kernel_launch(void* const* d_in, const int* in_sizes, int n_in,
                              void* d_out, int out_size)
{
    const float* sig    = (const float*)d_in[0];  // (64, 273, 3000) f32
    const float* pos    = (const float*)d_in[1];  // (64, 273, 2)    f32
    const float* center = (const float*)d_in[2];  // (2,)            f32
    const float* mc     = (const float*)d_in[3];  // (100, 2)        f32
    float* out          = (float*)d_out;

    fused_kernel<<<ROWS, 256>>>(sig, pos, center, mc, out);
}

// round 5
// speedup vs baseline: 3.3446x; 1.0005x over previous
#include <cuda_runtime.h>

// ChannelDropout — fused, barrier-free, streaming-hinted:
//   2 rows per block (512 threads). Threads 0-255 own row 2b, threads 256-511
//   own row 2b+1; each thread handles up to 3 float4 of its row.
//   MC keep-count computed warp-cooperatively via 4 ballots (no smem/barriers).
//   __ldcs/__stcs mark the 420MB stream evict-first (zero reuse).

#define DROPOUT2 0.04f   // 0.2^2
#define EPSILON  1e-8f
#define T4       750     // 3000 floats / 4
#define ROWS     (64 * 273)   // 17472

__global__ __launch_bounds__(512, 4)
void fused_kernel(const float* __restrict__ sig,
                  const float* __restrict__ pos,
                  const float* __restrict__ center,
                  const float* __restrict__ mc,
                  float* __restrict__ out)
{
    const int tid  = threadIdx.x;
    const int half = tid >> 8;                 // 0 or 1
    const int t    = tid & 255;                // index within the row's 256 threads
    const int row  = blockIdx.x * 2 + half;
    const int lane = tid & 31;

    const float4* __restrict__ s4 = (const float4*)(sig) + (size_t)row * T4;
    float4*       __restrict__ o4 = (float4*)(out)       + (size_t)row * T4;

    // --- issue row loads first (independent of the scalar work) ---
    const int i0 = t;
    const int i1 = t + 256;
    const int i2 = t + 512;
    const bool has2 = (i2 < T4);               // t < 238

    float4 v0 = __ldcs(&s4[i0]);
    float4 v1 = __ldcs(&s4[i1]);
    float4 v2 = has2 ? __ldcs(&s4[i2]) : make_float4(0.f, 0.f, 0.f, 0.f);

    // --- per-row scalar, warp-cooperative (each warp is entirely in one row) ---
    const float px = __ldg(&pos[row * 2 + 0]);
    const float py = __ldg(&pos[row * 2 + 1]);
    const float cx = __ldg(&center[0]);
    const float cy = __ldg(&center[1]);

    float ax, ay;
    ax = px - __ldg(&mc[2 * lane + 0]);
    ay = py - __ldg(&mc[2 * lane + 1]);
    const bool f0 = (ax * ax + ay * ay) > DROPOUT2;

    ax = px - __ldg(&mc[2 * (lane + 32) + 0]);
    ay = py - __ldg(&mc[2 * (lane + 32) + 1]);
    const bool f1 = (ax * ax + ay * ay) > DROPOUT2;

    ax = px - __ldg(&mc[2 * (lane + 64) + 0]);
    ay = py - __ldg(&mc[2 * (lane + 64) + 1]);
    const bool f2 = (ax * ax + ay * ay) > DROPOUT2;

    bool f3 = false;
    if (lane < 4) {
        ax = px - __ldg(&mc[2 * (lane + 96) + 0]);
        ay = py - __ldg(&mc[2 * (lane + 96) + 1]);
        f3 = (ax * ax + ay * ay) > DROPOUT2;
    }

    const unsigned b0 = __ballot_sync(0xFFFFFFFFu, f0);
    const unsigned b1 = __ballot_sync(0xFFFFFFFFu, f1);
    const unsigned b2 = __ballot_sync(0xFFFFFFFFu, f2);
    const unsigned b3 = __ballot_sync(0xFFFFFFFFu, f3);

    const int cnt = __popc(b0) + __popc(b1) + __popc(b2) + __popc(b3 & 0xFu);

    const float dx = px - cx, dy = py - cy;
    const bool kept = (dx * dx + dy * dy) > DROPOUT2;

    const float proba = __int2float_rn(cnt) * 0.01f;
    const float scale = kept ? (1.0f / (EPSILON + proba)) : 0.0f;

    // --- scale + streaming store ---
    v0.x *= scale; v0.y *= scale; v0.z *= scale; v0.w *= scale;
    v1.x *= scale; v1.y *= scale; v1.z *= scale; v1.w *= scale;
    __stcs(&o4[i0], v0);
    __stcs(&o4[i1], v1);
    if (has2) {
        v2.x *= scale; v2.y *= scale; v2.z *= scale; v2.w *= scale;
        __stcs(&o4[i2], v2);
    }
}

extern "C" void kernel_launch(void* const* d_in, const int* in_sizes, int n_in,
                              void* d_out, int out_size)
{
    const float* sig    = (const float*)d_in[0];  // (64, 273, 3000) f32
    const float* pos    = (const float*)d_in[1];  // (64, 273, 2)    f32
    const float* center = (const float*)d_in[2];  // (2,)            f32
    const float* mc     = (const float*)d_in[3];  // (100, 2)        f32
    float* out          = (float*)d_out;

    fused_kernel<<<ROWS / 2, 512>>>(sig, pos, center, mc, out);
}

// round 7
// speedup vs baseline: 3.4489x; 1.0312x over previous
#include <cuda_runtime.h>

// ChannelDropout — fused, with dropped-row read elision:
//   One block (256 thr) per row. kept(row) needs only pos+center, so it's
//   computed BEFORE the signal loads. Dropped rows (~11% of rows: dist<=0.2
//   from center) write zeros without ever reading their 12KB of signal —
//   a ~6% total-traffic reduction on an HBM-bound stream.
//   Kept rows: 3x LDG.128 issued first, MC keep-count via 4 warp ballots
//   (no smem / no barriers) hides under the loads.

#define DROPOUT2 0.04f   // 0.2^2
#define EPSILON  1e-8f
#define T4       750     // 3000 floats / 4
#define ROWS     (64 * 273)   // 17472

__global__ __launch_bounds__(256, 8)
void fused_kernel(const float* __restrict__ sig,
                  const float* __restrict__ pos,
                  const float* __restrict__ center,
                  const float* __restrict__ mc,
                  float* __restrict__ out)
{
    const int row  = blockIdx.x;
    const int tid  = threadIdx.x;
    const int lane = tid & 31;

    float4* __restrict__ o4 = (float4*)(out) + (size_t)row * T4;

    const int i0 = tid;
    const int i1 = tid + 256;
    const int i2 = tid + 512;
    const bool has2 = (i2 < T4);               // tid < 238

    // --- kept check first: only pos + center needed (block-uniform branch) ---
    const float px = __ldg(&pos[row * 2 + 0]);
    const float py = __ldg(&pos[row * 2 + 1]);
    const float cx = __ldg(&center[0]);
    const float cy = __ldg(&center[1]);

    const float dx = px - cx, dy = py - cy;
    const bool kept = (dx * dx + dy * dy) > DROPOUT2;

    if (!kept) {
        // Dropped row: zero output, skip signal reads AND the MC loop entirely.
        const float4 z = make_float4(0.f, 0.f, 0.f, 0.f);
        __stcs(&o4[i0], z);
        __stcs(&o4[i1], z);
        if (has2) __stcs(&o4[i2], z);
        return;
    }

    // --- kept row: issue signal loads immediately ---
    const float4* __restrict__ s4 = (const float4*)(sig) + (size_t)row * T4;
    float4 v0 = __ldcs(&s4[i0]);
    float4 v1 = __ldcs(&s4[i1]);
    float4 v2 = has2 ? __ldcs(&s4[i2]) : make_float4(0.f, 0.f, 0.f, 0.f);

    // --- MC keep-count, warp-cooperative (hides under the in-flight loads) ---
    float ax, ay;
    ax = px - __ldg(&mc[2 * lane + 0]);
    ay = py - __ldg(&mc[2 * lane + 1]);
    const bool f0 = (ax * ax + ay * ay) > DROPOUT2;

    ax = px - __ldg(&mc[2 * (lane + 32) + 0]);
    ay = py - __ldg(&mc[2 * (lane + 32) + 1]);
    const bool f1 = (ax * ax + ay * ay) > DROPOUT2;

    ax = px - __ldg(&mc[2 * (lane + 64) + 0]);
    ay = py - __ldg(&mc[2 * (lane + 64) + 1]);
    const bool f2 = (ax * ax + ay * ay) > DROPOUT2;

    bool f3 = false;
    if (lane < 4) {
        ax = px - __ldg(&mc[2 * (lane + 96) + 0]);
        ay = py - __ldg(&mc[2 * (lane + 96) + 1]);
        f3 = (ax * ax + ay * ay) > DROPOUT2;
    }

    const unsigned b0 = __ballot_sync(0xFFFFFFFFu, f0);
    const unsigned b1 = __ballot_sync(0xFFFFFFFFu, f1);
    const unsigned b2 = __ballot_sync(0xFFFFFFFFu, f2);
    const unsigned b3 = __ballot_sync(0xFFFFFFFFu, f3);

    const int cnt = __popc(b0) + __popc(b1) + __popc(b2) + __popc(b3 & 0xFu);

    const float proba = __int2float_rn(cnt) * 0.01f;
    const float scale = 1.0f / (EPSILON + proba);

    // --- scale + streaming store ---
    v0.x *= scale; v0.y *= scale; v0.z *= scale; v0.w *= scale;
    v1.x *= scale; v1.y *= scale; v1.z *= scale; v1.w *= scale;
    __stcs(&o4[i0], v0);
    __stcs(&o4[i1], v1);
    if (has2) {
        v2.x *= scale; v2.y *= scale; v2.z *= scale; v2.w *= scale;
        __stcs(&o4[i2], v2);
    }
}

extern "C" void kernel_launch(void* const* d_in, const int* in_sizes, int n_in,
                              void* d_out, int out_size)
{
    const float* sig    = (const float*)d_in[0];  // (64, 273, 3000) f32
    const float* pos    = (const float*)d_in[1];  // (64, 273, 2)    f32
    const float* center = (const float*)d_in[2];  // (2,)            f32
    const float* mc     = (const float*)d_in[3];  // (100, 2)        f32
    float* out          = (float*)d_out;

    fused_kernel<<<ROWS, 256>>>(sig, pos, center, mc, out);
}